// round 2
// baseline (speedup 1.0000x reference)
#include <cuda_runtime.h>
#include <cuda_bf16.h>
#include <math.h>
#include <stdint.h>

// ---------------------------------------------------------------------------
// Problem constants
// ---------------------------------------------------------------------------
#define T_TOK 2048
#define HID   5120
#define NHEAD 16
#define QL    1536
#define KL    512
#define NOPE  128
#define ROPE  64
#define VD    128
#define QK    192      // NOPE + ROPE
#define KVD   256      // NOPE + VD
#define LATW  576      // KL + ROPE

// ---------------------------------------------------------------------------
// Scratch (static device memory; no allocations allowed)
// ---------------------------------------------------------------------------
__device__ float g_qa  [T_TOK * QL];            // q_a (then rms-normed in place)
__device__ float g_q   [T_TOK * NHEAD * QK];    // q projected, rope applied in place
__device__ float g_lat [T_TOK * LATW];          // hidden @ w_kv_a
__device__ float g_kvn [T_TOK * KL];            // rms(kv_a)
__device__ float g_kv  [T_TOK * NHEAD * KVD];   // kv projected (k_nope | v)
__device__ float g_kpe [T_TOK * ROPE];          // rope'd shared k_pe
__device__ float g_att [T_TOK * NHEAD * VD];    // attention output [T, H*VD]

// ---------------------------------------------------------------------------
// Generic fp32 tiled GEMM: C[M,N] = A[M,K] @ B[K,N], all row-major.
// Requires M%64==0, N%64==0, K%16==0 (true for every GEMM here).
// ---------------------------------------------------------------------------
__global__ __launch_bounds__(256) void gemm_kernel(
    const float* __restrict__ A, const float* __restrict__ B,
    float* __restrict__ C, int M, int N, int K)
{
    __shared__ float As[64][17];
    __shared__ float Bs[16][68];

    const int tid = threadIdx.x;
    const int tx  = tid & 15;        // 0..15 -> 4 cols each
    const int ty  = tid >> 4;        // 0..15 -> 4 rows each
    const int rowBase = blockIdx.y * 64;
    const int colBase = blockIdx.x * 64;

    const float* Ab = A + (size_t)rowBase * K;
    const float* Bb = B + colBase;

    float acc[4][4] = {};

    for (int k0 = 0; k0 < K; k0 += 16) {
        // Stage A tile 64x16 (float4 per thread)
        {
            int r = tid >> 2;
            int c = (tid & 3) << 2;
            float4 v = *reinterpret_cast<const float4*>(Ab + (size_t)r * K + k0 + c);
            As[r][c + 0] = v.x; As[r][c + 1] = v.y;
            As[r][c + 2] = v.z; As[r][c + 3] = v.w;
        }
        // Stage B tile 16x64 (float4 per thread)
        {
            int r = tid >> 4;
            int c = (tid & 15) << 2;
            float4 v = *reinterpret_cast<const float4*>(Bb + (size_t)(k0 + r) * N + c);
            *reinterpret_cast<float4*>(&Bs[r][c]) = v;
        }
        __syncthreads();

        #pragma unroll
        for (int k = 0; k < 16; k++) {
            float a0 = As[ty * 4 + 0][k];
            float a1 = As[ty * 4 + 1][k];
            float a2 = As[ty * 4 + 2][k];
            float a3 = As[ty * 4 + 3][k];
            float4 b = *reinterpret_cast<float4*>(&Bs[k][tx * 4]);
            acc[0][0] += a0 * b.x; acc[0][1] += a0 * b.y; acc[0][2] += a0 * b.z; acc[0][3] += a0 * b.w;
            acc[1][0] += a1 * b.x; acc[1][1] += a1 * b.y; acc[1][2] += a1 * b.z; acc[1][3] += a1 * b.w;
            acc[2][0] += a2 * b.x; acc[2][1] += a2 * b.y; acc[2][2] += a2 * b.z; acc[2][3] += a2 * b.w;
            acc[3][0] += a3 * b.x; acc[3][1] += a3 * b.y; acc[3][2] += a3 * b.z; acc[3][3] += a3 * b.w;
        }
        __syncthreads();
    }

    #pragma unroll
    for (int i = 0; i < 4; i++) {
        float4 v = make_float4(acc[i][0], acc[i][1], acc[i][2], acc[i][3]);
        *reinterpret_cast<float4*>(
            C + (size_t)(rowBase + ty * 4 + i) * N + colBase + tx * 4) = v;
    }
}

// ---------------------------------------------------------------------------
// RMSNorm: one block per row. y = x * rsqrt(mean(x^2)+eps) * w
// ---------------------------------------------------------------------------
__global__ __launch_bounds__(256) void rmsnorm_kernel(
    const float* __restrict__ x, const float* __restrict__ w,
    float* __restrict__ y, int width, int xstride, int ystride)
{
    const int row = blockIdx.x;
    const float* xr = x + (size_t)row * xstride;
    float* yr       = y + (size_t)row * ystride;

    float ss = 0.f;
    for (int i = threadIdx.x; i < width; i += blockDim.x) {
        float v = xr[i];
        ss += v * v;
    }
    // block reduce
    __shared__ float red[8];
    for (int o = 16; o; o >>= 1) ss += __shfl_xor_sync(0xffffffffu, ss, o);
    if ((threadIdx.x & 31) == 0) red[threadIdx.x >> 5] = ss;
    __syncthreads();
    __shared__ float s_r;
    if (threadIdx.x == 0) {
        float tot = 0.f;
        for (int i = 0; i < (int)(blockDim.x >> 5); i++) tot += red[i];
        s_r = rsqrtf(tot / (float)width + 1e-6f);
    }
    __syncthreads();
    float r = s_r;
    for (int i = threadIdx.x; i < width; i += blockDim.x)
        yr[i] = xr[i] * r * w[i];
}

// ---------------------------------------------------------------------------
// RoPE (YaRN): one block per token, 64 threads.
// Computes inv_freq in double (matches numpy f64 path), applies interleaved
// rotation to q_pe (all heads, in place in g_q) and k_pe (-> g_kpe).
// cos_sin_mscale == 1.0 for these params (mscale == mscale_all_dim).
// ---------------------------------------------------------------------------
__global__ __launch_bounds__(64) void rope_kernel(
    const int* __restrict__ positions,
    float* __restrict__ q,           // [T, H, QK]
    const float* __restrict__ lat,   // [T, LATW]
    float* __restrict__ kpe)         // [T, ROPE]
{
    const int t = blockIdx.x;
    __shared__ float cs[32], sn[32];

    if (threadIdx.x < 32) {
        int i = threadIdx.x;
        // YaRN inv_freq (double precision, matches reference numpy)
        double pf    = pow(10000.0, (double)(2 * i) / (double)ROPE);
        double extra = 1.0 / pf;
        double inter = 1.0 / (40.0 * pf);
        double lowd  = floor((double)ROPE * log(4096.0 / (32.0 * 2.0 * M_PI)) / (2.0 * log(10000.0)));
        double highd = ceil ((double)ROPE * log(4096.0 / ( 1.0 * 2.0 * M_PI)) / (2.0 * log(10000.0)));
        if (lowd < 0.0) lowd = 0.0;
        if (highd > (double)(ROPE - 1)) highd = (double)(ROPE - 1);
        double denom = highd - lowd; if (denom < 0.001) denom = 0.001;
        double ramp  = ((double)i - lowd) / denom;
        if (ramp < 0.0) ramp = 0.0;
        if (ramp > 1.0) ramp = 1.0;
        double mask = 1.0 - ramp;
        float invf = (float)(inter * (1.0 - mask) + extra * mask);

        float freq = (float)positions[t] * invf;   // f32 product, like reference
        cs[i] = (float)cos((double)freq);
        sn[i] = (float)sin((double)freq);
    }
    __syncthreads();

    for (int p = threadIdx.x; p < (NHEAD + 1) * 32; p += 64) {
        int i = p & 31;
        int h = p >> 5;
        float c = cs[i], s = sn[i];
        if (h < NHEAD) {
            float* base = q + ((size_t)t * NHEAD + h) * QK + NOPE + 2 * i;
            float x1 = base[0], x2 = base[1];
            base[0] = x1 * c - x2 * s;
            base[1] = x2 * c + x1 * s;
        } else {
            const float* kb = lat + (size_t)t * LATW + KL + 2 * i;
            float x1 = kb[0], x2 = kb[1];
            kpe[(size_t)t * ROPE + 2 * i]     = x1 * c - x2 * s;
            kpe[(size_t)t * ROPE + 2 * i + 1] = x2 * c + x1 * s;
        }
    }
}

// ---------------------------------------------------------------------------
// Causal flash attention, fp32. Grid: (T/8, H). 8 warps, warp w owns query
// q0+w. Keys streamed in 32-key tiles through shared memory; lane j owns
// key j's score; V accumulation is lane-strided over the 128 v-dims.
// ---------------------------------------------------------------------------
__global__ __launch_bounds__(256) void attn_kernel(
    const float* __restrict__ q,    // [T, H, QK] (rope applied)
    const float* __restrict__ kv,   // [T, H, KVD] (k_nope | v)
    const float* __restrict__ kpe,  // [T, ROPE]
    float* __restrict__ out,        // [T, H*VD]
    float scale)
{
    __shared__ float Ks[32][193];   // stride 193: conflict-free row reads
    __shared__ float Vs[32][129];
    __shared__ float Qs[8][QK];

    const int h    = blockIdx.y;
    const int q0   = blockIdx.x * 8;
    const int tid  = threadIdx.x;
    const int w    = tid >> 5;
    const int lane = tid & 31;
    const int qi   = q0 + w;

    for (int idx = tid; idx < 8 * QK; idx += 256) {
        int r = idx / QK, d = idx - r * QK;
        Qs[r][d] = q[((size_t)(q0 + r) * NHEAD + h) * QK + d];
    }

    float acc0 = 0.f, acc1 = 0.f, acc2 = 0.f, acc3 = 0.f;
    float m = -INFINITY, l = 0.f;

    const int nkb = (q0 + 7) / 32 + 1;
    for (int kb = 0; kb < nkb; kb++) {
        const int k0 = kb * 32;
        __syncthreads();
        for (int idx = tid; idx < 32 * QK; idx += 256) {
            int r = idx / QK, d = idx - r * QK;
            float v;
            if (d < NOPE) v = kv[((size_t)(k0 + r) * NHEAD + h) * KVD + d];
            else          v = kpe[(size_t)(k0 + r) * ROPE + (d - NOPE)];
            Ks[r][d] = v;
        }
        for (int idx = tid; idx < 32 * VD; idx += 256) {
            int r = idx >> 7, d = idx & 127;
            Vs[r][d] = kv[((size_t)(k0 + r) * NHEAD + h) * KVD + NOPE + d];
        }
        __syncthreads();

        // score for key (k0 + lane)
        float s = 0.f;
        #pragma unroll 8
        for (int d = 0; d < QK; d++) s += Qs[w][d] * Ks[lane][d];
        s *= scale;
        if (k0 + lane > qi) s = -INFINITY;

        float mb = s;
        for (int o = 16; o; o >>= 1) mb = fmaxf(mb, __shfl_xor_sync(0xffffffffu, mb, o));
        float mnew = fmaxf(m, mb);
        float p = expf(s - mnew);                 // -inf -> 0
        float psum = p;
        for (int o = 16; o; o >>= 1) psum += __shfl_xor_sync(0xffffffffu, psum, o);
        float alpha = expf(m - mnew);             // first tile: exp(-inf)=0
        l = l * alpha + psum;
        acc0 *= alpha; acc1 *= alpha; acc2 *= alpha; acc3 *= alpha;

        #pragma unroll
        for (int j = 0; j < 32; j++) {
            float pj = __shfl_sync(0xffffffffu, p, j);
            acc0 += pj * Vs[j][lane];
            acc1 += pj * Vs[j][lane + 32];
            acc2 += pj * Vs[j][lane + 64];
            acc3 += pj * Vs[j][lane + 96];
        }
        m = mnew;
    }

    const float inv = 1.f / l;
    const size_t ob = (size_t)qi * (NHEAD * VD) + (size_t)h * VD;
    out[ob + lane]      = acc0 * inv;
    out[ob + lane + 32] = acc1 * inv;
    out[ob + lane + 64] = acc2 * inv;
    out[ob + lane + 96] = acc3 * inv;
}

// ---------------------------------------------------------------------------
// Launch
// ---------------------------------------------------------------------------
extern "C" void kernel_launch(void* const* d_in, const int* in_sizes, int n_in,
                              void* d_out, int out_size)
{
    const int*   positions = (const int*)  d_in[0];
    const float* hidden    = (const float*)d_in[1];
    const float* w_q_a     = (const float*)d_in[2];
    const float* q_a_norm  = (const float*)d_in[3];
    const float* w_q_b     = (const float*)d_in[4];
    const float* w_kv_a    = (const float*)d_in[5];
    const float* kv_a_norm = (const float*)d_in[6];
    const float* w_kv_b    = (const float*)d_in[7];
    const float* w_o       = (const float*)d_in[8];
    float* out = (float*)d_out;

    void *p_qa, *p_q, *p_lat, *p_kvn, *p_kv, *p_kpe, *p_att;
    cudaGetSymbolAddress(&p_qa,  g_qa);
    cudaGetSymbolAddress(&p_q,   g_q);
    cudaGetSymbolAddress(&p_lat, g_lat);
    cudaGetSymbolAddress(&p_kvn, g_kvn);
    cudaGetSymbolAddress(&p_kv,  g_kv);
    cudaGetSymbolAddress(&p_kpe, g_kpe);
    cudaGetSymbolAddress(&p_att, g_att);
    float* qa  = (float*)p_qa;
    float* qb  = (float*)p_q;
    float* lat = (float*)p_lat;
    float* kvn = (float*)p_kvn;
    float* kv  = (float*)p_kv;
    float* kpe = (float*)p_kpe;
    float* att = (float*)p_att;

    // ATTN_SCALE = QK^-0.5 * m^2, m = 0.1*ln(40)+1
    const double mm = 0.1 * log(40.0) + 1.0;
    const float attn_scale = (float)(mm * mm / sqrt((double)QK));

    // q_a = hidden @ w_q_a
    gemm_kernel<<<dim3(QL / 64, T_TOK / 64), 256>>>(hidden, w_q_a, qa, T_TOK, QL, HID);
    // lat = hidden @ w_kv_a
    gemm_kernel<<<dim3(LATW / 64, T_TOK / 64), 256>>>(hidden, w_kv_a, lat, T_TOK, LATW, HID);
    // rms(q_a) in place
    rmsnorm_kernel<<<T_TOK, 256>>>(qa, q_a_norm, qa, QL, QL, QL);
    // q = rms(q_a) @ w_q_b
    gemm_kernel<<<dim3(NHEAD * QK / 64, T_TOK / 64), 256>>>(qa, w_q_b, qb, T_TOK, NHEAD * QK, QL);
    // kvn = rms(lat[:, :KL])
    rmsnorm_kernel<<<T_TOK, 256>>>(lat, kv_a_norm, kvn, KL, LATW, KL);
    // kv = kvn @ w_kv_b
    gemm_kernel<<<dim3(NHEAD * KVD / 64, T_TOK / 64), 256>>>(kvn, w_kv_b, kv, T_TOK, NHEAD * KVD, KL);
    // rope q_pe (in place) + k_pe
    rope_kernel<<<T_TOK, 64>>>(positions, qb, lat, kpe);
    // attention -> att [T, H*VD]
    attn_kernel<<<dim3(T_TOK / 8, NHEAD), 256>>>(qb, kv, kpe, att, attn_scale);
    // out = att @ w_o
    gemm_kernel<<<dim3(HID / 64, T_TOK / 64), 256>>>(att, w_o, out, T_TOK, HID, NHEAD * VD);
}

// round 3
// speedup vs baseline: 1.2879x; 1.2879x over previous
#include <cuda_runtime.h>
#include <cuda_bf16.h>
#include <math.h>
#include <stdint.h>

// ---------------------------------------------------------------------------
// Problem constants
// ---------------------------------------------------------------------------
#define T_TOK 2048
#define HID   5120
#define NHEAD 16
#define QL    1536
#define KL    512
#define NOPE  128
#define ROPE  64
#define VD    128
#define QK    192      // NOPE + ROPE
#define KVD   256      // NOPE + VD
#define LATW  576      // KL + ROPE

// ---------------------------------------------------------------------------
// Scratch (static device memory; no allocations allowed)
// ---------------------------------------------------------------------------
__device__ float g_qa  [T_TOK * QL];
__device__ float g_q   [T_TOK * NHEAD * QK];
__device__ float g_lat [T_TOK * LATW];
__device__ float g_kvn [T_TOK * KL];
__device__ float g_kv  [T_TOK * NHEAD * KVD];
__device__ float g_kpe [T_TOK * ROPE];
__device__ float g_att [T_TOK * NHEAD * VD];

// ---------------------------------------------------------------------------
// fp32 GEMM, 128xBN tile, BK=8, 8x(BN/16) per thread, double-buffered smem.
// Requires M%128==0, N%BN==0, K%8==0 (holds for every GEMM here).
// ---------------------------------------------------------------------------
template<int BN>
__global__ __launch_bounds__(256) void gemm_tc(
    const float* __restrict__ A, const float* __restrict__ B,
    float* __restrict__ C, int M, int N, int K)
{
    constexpr int TN = BN / 16;            // 8 or 4
    constexpr int BELEM = BN / 32;         // B floats per thread per tile (4 or 2)

    __shared__ float As[2][8][128];
    __shared__ float Bs[2][8][BN];

    const int tid = threadIdx.x;
    const int ty  = tid >> 4;              // 0..15
    const int tx  = tid & 15;              // 0..15
    const int rowBase = blockIdx.y * 128;
    const int colBase = blockIdx.x * BN;

    // A tile load mapping: 128x8 floats, float4 per thread
    const int ar = tid >> 1;               // 0..127
    const int ak = (tid & 1) * 4;          // 0 or 4
    // B tile load mapping: 8xBN floats
    const int br = tid >> 5;               // 0..7
    const int bc = (tid & 31) * BELEM;

    const float* Aptr = A + (size_t)(rowBase + ar) * K + ak;
    const float* Bptr = B + (size_t)br * N + colBase + bc;

    float4 aReg;
    float  bReg[BELEM];

    // ---- prologue: tile 0 ----
    aReg = *reinterpret_cast<const float4*>(Aptr);
    if (BELEM == 4) {
        float4 v = *reinterpret_cast<const float4*>(Bptr);
        bReg[0] = v.x; bReg[1] = v.y; bReg[2] = v.z; bReg[3] = v.w;
    } else {
        float2 v = *reinterpret_cast<const float2*>(Bptr);
        bReg[0] = v.x; bReg[1] = v.y;
    }
    As[0][ak + 0][ar] = aReg.x;
    As[0][ak + 1][ar] = aReg.y;
    As[0][ak + 2][ar] = aReg.z;
    As[0][ak + 3][ar] = aReg.w;
    #pragma unroll
    for (int j = 0; j < BELEM; j++) Bs[0][br][bc + j] = bReg[j];
    __syncthreads();

    float acc[8][TN];
    #pragma unroll
    for (int i = 0; i < 8; i++)
        #pragma unroll
        for (int j = 0; j < TN; j++) acc[i][j] = 0.f;

    const int nk = K >> 3;
    int p = 0;
    for (int kt = 0; kt < nk; kt++) {
        const bool more = (kt + 1 < nk);
        if (more) {
            aReg = *reinterpret_cast<const float4*>(Aptr + (kt + 1) * 8);
            const float* bp = Bptr + (size_t)(kt + 1) * 8 * N;
            if (BELEM == 4) {
                float4 v = *reinterpret_cast<const float4*>(bp);
                bReg[0] = v.x; bReg[1] = v.y; bReg[2] = v.z; bReg[3] = v.w;
            } else {
                float2 v = *reinterpret_cast<const float2*>(bp);
                bReg[0] = v.x; bReg[1] = v.y;
            }
        }

        #pragma unroll
        for (int k = 0; k < 8; k++) {
            float af[8], bf[TN];
            #pragma unroll
            for (int i = 0; i < 8; i += 4)
                *reinterpret_cast<float4*>(&af[i]) =
                    *reinterpret_cast<const float4*>(&As[p][k][ty * 8 + i]);
            #pragma unroll
            for (int j = 0; j < TN; j += 4)
                *reinterpret_cast<float4*>(&bf[j]) =
                    *reinterpret_cast<const float4*>(&Bs[p][k][tx * TN + j]);
            #pragma unroll
            for (int i = 0; i < 8; i++)
                #pragma unroll
                for (int j = 0; j < TN; j++)
                    acc[i][j] += af[i] * bf[j];
        }

        if (more) {
            const int np = 1 - p;
            As[np][ak + 0][ar] = aReg.x;
            As[np][ak + 1][ar] = aReg.y;
            As[np][ak + 2][ar] = aReg.z;
            As[np][ak + 3][ar] = aReg.w;
            #pragma unroll
            for (int j = 0; j < BELEM; j++) Bs[np][br][bc + j] = bReg[j];
            __syncthreads();
            p = np;
        }
    }

    // ---- epilogue ----
    #pragma unroll
    for (int i = 0; i < 8; i++) {
        float* cp = C + (size_t)(rowBase + ty * 8 + i) * N + colBase + tx * TN;
        #pragma unroll
        for (int j = 0; j < TN; j += 4) {
            float4 v = make_float4(acc[i][j], acc[i][j + 1], acc[i][j + 2], acc[i][j + 3]);
            *reinterpret_cast<float4*>(cp + j) = v;
        }
    }
}

// ---------------------------------------------------------------------------
// RMSNorm: one block per row.
// ---------------------------------------------------------------------------
__global__ __launch_bounds__(256) void rmsnorm_kernel(
    const float* __restrict__ x, const float* __restrict__ w,
    float* __restrict__ y, int width, int xstride, int ystride)
{
    const int row = blockIdx.x;
    const float* xr = x + (size_t)row * xstride;
    float* yr       = y + (size_t)row * ystride;

    float ss = 0.f;
    for (int i = threadIdx.x; i < width; i += blockDim.x) {
        float v = xr[i];
        ss += v * v;
    }
    __shared__ float red[8];
    for (int o = 16; o; o >>= 1) ss += __shfl_xor_sync(0xffffffffu, ss, o);
    if ((threadIdx.x & 31) == 0) red[threadIdx.x >> 5] = ss;
    __syncthreads();
    __shared__ float s_r;
    if (threadIdx.x == 0) {
        float tot = 0.f;
        for (int i = 0; i < (int)(blockDim.x >> 5); i++) tot += red[i];
        s_r = rsqrtf(tot / (float)width + 1e-6f);
    }
    __syncthreads();
    float r = s_r;
    for (int i = threadIdx.x; i < width; i += blockDim.x)
        yr[i] = xr[i] * r * w[i];
}

// ---------------------------------------------------------------------------
// RoPE (YaRN), double-precision inv_freq to match numpy path.
// ---------------------------------------------------------------------------
__global__ __launch_bounds__(64) void rope_kernel(
    const int* __restrict__ positions,
    float* __restrict__ q,
    const float* __restrict__ lat,
    float* __restrict__ kpe)
{
    const int t = blockIdx.x;
    __shared__ float cs[32], sn[32];

    if (threadIdx.x < 32) {
        int i = threadIdx.x;
        double pf    = pow(10000.0, (double)(2 * i) / (double)ROPE);
        double extra = 1.0 / pf;
        double inter = 1.0 / (40.0 * pf);
        double lowd  = floor((double)ROPE * log(4096.0 / (32.0 * 2.0 * M_PI)) / (2.0 * log(10000.0)));
        double highd = ceil ((double)ROPE * log(4096.0 / ( 1.0 * 2.0 * M_PI)) / (2.0 * log(10000.0)));
        if (lowd < 0.0) lowd = 0.0;
        if (highd > (double)(ROPE - 1)) highd = (double)(ROPE - 1);
        double denom = highd - lowd; if (denom < 0.001) denom = 0.001;
        double ramp  = ((double)i - lowd) / denom;
        if (ramp < 0.0) ramp = 0.0;
        if (ramp > 1.0) ramp = 1.0;
        double mask = 1.0 - ramp;
        float invf = (float)(inter * (1.0 - mask) + extra * mask);

        float freq = (float)positions[t] * invf;
        cs[i] = (float)cos((double)freq);
        sn[i] = (float)sin((double)freq);
    }
    __syncthreads();

    for (int p = threadIdx.x; p < (NHEAD + 1) * 32; p += 64) {
        int i = p & 31;
        int h = p >> 5;
        float c = cs[i], s = sn[i];
        if (h < NHEAD) {
            float* base = q + ((size_t)t * NHEAD + h) * QK + NOPE + 2 * i;
            float x1 = base[0], x2 = base[1];
            base[0] = x1 * c - x2 * s;
            base[1] = x2 * c + x1 * s;
        } else {
            const float* kb = lat + (size_t)t * LATW + KL + 2 * i;
            float x1 = kb[0], x2 = kb[1];
            kpe[(size_t)t * ROPE + 2 * i]     = x1 * c - x2 * s;
            kpe[(size_t)t * ROPE + 2 * i + 1] = x2 * c + x1 * s;
        }
    }
}

// ---------------------------------------------------------------------------
// Causal flash attention v2, fp32, fully float4.
// Grid: (T/16, H). 256 threads; warp w owns queries q0+2w, q0+2w+1.
// 32-key tiles; lane j owns key j's scores; V accumulated as float4 per lane.
// Dynamic smem: Qs[16][49] + Ks[32][49] + Vs[32][33] float4 = 54528 B.
// ---------------------------------------------------------------------------
#define ATTN_SMEM_F4 (16 * 49 + 32 * 49 + 32 * 33)

__global__ __launch_bounds__(256) void attn_kernel(
    const float* __restrict__ q,
    const float* __restrict__ kv,
    const float* __restrict__ kpe,
    float* __restrict__ out,
    float scale)
{
    extern __shared__ float4 sm[];
    float4* Qs = sm;                    // [16][49], 48 used per row
    float4* Ks = sm + 16 * 49;          // [32][49], 48 used per row
    float4* Vs = sm + 16 * 49 + 32 * 49;// [32][33], 32 used per row

    const int h    = blockIdx.y;
    const int q0   = blockIdx.x * 16;
    const int tid  = threadIdx.x;
    const int w    = tid >> 5;
    const int lane = tid & 31;
    const int qiA  = q0 + 2 * w;
    const int qiB  = qiA + 1;

    for (int idx = tid; idx < 16 * 48; idx += 256) {
        int r = idx / 48, d = idx - r * 48;
        Qs[r * 49 + d] =
            reinterpret_cast<const float4*>(q + ((size_t)(q0 + r) * NHEAD + h) * QK)[d];
    }

    float4 accA = make_float4(0.f, 0.f, 0.f, 0.f);
    float4 accB = make_float4(0.f, 0.f, 0.f, 0.f);
    float mA = -1e30f, lA = 0.f, mB = -1e30f, lB = 0.f;

    const int nkb = (q0 + 15) / 32 + 1;
    for (int kb = 0; kb < nkb; kb++) {
        const int k0 = kb * 32;
        __syncthreads();
        for (int idx = tid; idx < 32 * 48; idx += 256) {
            int r = idx / 48, d = idx - r * 48;
            float4 v;
            if (d < 32)
                v = reinterpret_cast<const float4*>(kv + ((size_t)(k0 + r) * NHEAD + h) * KVD)[d];
            else
                v = reinterpret_cast<const float4*>(kpe + (size_t)(k0 + r) * ROPE)[d - 32];
            Ks[r * 49 + d] = v;
        }
        for (int idx = tid; idx < 32 * 32; idx += 256) {
            int r = idx >> 5, d = idx & 31;
            Vs[r * 33 + d] =
                reinterpret_cast<const float4*>(kv + ((size_t)(k0 + r) * NHEAD + h) * KVD + NOPE)[d];
        }
        __syncthreads();

        // scores for key (k0 + lane), both queries
        float sA = 0.f, sB = 0.f;
        const float4* kr = &Ks[lane * 49];
        const float4* qr0 = &Qs[(2 * w) * 49];
        const float4* qr1 = &Qs[(2 * w + 1) * 49];
        #pragma unroll
        for (int d = 0; d < 48; d++) {
            float4 kvv = kr[d];
            float4 q1 = qr0[d];
            float4 q2 = qr1[d];
            sA += q1.x * kvv.x + q1.y * kvv.y + q1.z * kvv.z + q1.w * kvv.w;
            sB += q2.x * kvv.x + q2.y * kvv.y + q2.z * kvv.z + q2.w * kvv.w;
        }
        sA *= scale; sB *= scale;
        const int kidx = k0 + lane;
        if (kidx > qiA) sA = -1e30f;
        if (kidx > qiB) sB = -1e30f;

        float mbA = sA, mbB = sB;
        #pragma unroll
        for (int o = 16; o; o >>= 1) {
            mbA = fmaxf(mbA, __shfl_xor_sync(0xffffffffu, mbA, o));
            mbB = fmaxf(mbB, __shfl_xor_sync(0xffffffffu, mbB, o));
        }
        float mnA = fmaxf(mA, mbA), mnB = fmaxf(mB, mbB);
        float pA = __expf(sA - mnA), pB = __expf(sB - mnB);
        float psA = pA, psB = pB;
        #pragma unroll
        for (int o = 16; o; o >>= 1) {
            psA += __shfl_xor_sync(0xffffffffu, psA, o);
            psB += __shfl_xor_sync(0xffffffffu, psB, o);
        }
        float aA = __expf(mA - mnA), aB = __expf(mB - mnB);
        lA = lA * aA + psA;  lB = lB * aB + psB;
        accA.x *= aA; accA.y *= aA; accA.z *= aA; accA.w *= aA;
        accB.x *= aB; accB.y *= aB; accB.z *= aB; accB.w *= aB;
        mA = mnA; mB = mnB;

        #pragma unroll
        for (int j = 0; j < 32; j++) {
            float pjA = __shfl_sync(0xffffffffu, pA, j);
            float pjB = __shfl_sync(0xffffffffu, pB, j);
            float4 vv = Vs[j * 33 + lane];
            accA.x += pjA * vv.x; accA.y += pjA * vv.y;
            accA.z += pjA * vv.z; accA.w += pjA * vv.w;
            accB.x += pjB * vv.x; accB.y += pjB * vv.y;
            accB.z += pjB * vv.z; accB.w += pjB * vv.w;
        }
    }

    const float ivA = 1.f / lA, ivB = 1.f / lB;
    float4 oA = make_float4(accA.x * ivA, accA.y * ivA, accA.z * ivA, accA.w * ivA);
    float4 oB = make_float4(accB.x * ivB, accB.y * ivB, accB.z * ivB, accB.w * ivB);
    *reinterpret_cast<float4*>(out + (size_t)qiA * (NHEAD * VD) + (size_t)h * VD + lane * 4) = oA;
    *reinterpret_cast<float4*>(out + (size_t)qiB * (NHEAD * VD) + (size_t)h * VD + lane * 4) = oB;
}

// ---------------------------------------------------------------------------
// Launch
// ---------------------------------------------------------------------------
extern "C" void kernel_launch(void* const* d_in, const int* in_sizes, int n_in,
                              void* d_out, int out_size)
{
    const int*   positions = (const int*)  d_in[0];
    const float* hidden    = (const float*)d_in[1];
    const float* w_q_a     = (const float*)d_in[2];
    const float* q_a_norm  = (const float*)d_in[3];
    const float* w_q_b     = (const float*)d_in[4];
    const float* w_kv_a    = (const float*)d_in[5];
    const float* kv_a_norm = (const float*)d_in[6];
    const float* w_kv_b    = (const float*)d_in[7];
    const float* w_o       = (const float*)d_in[8];
    float* out = (float*)d_out;

    void *p_qa, *p_q, *p_lat, *p_kvn, *p_kv, *p_kpe, *p_att;
    cudaGetSymbolAddress(&p_qa,  g_qa);
    cudaGetSymbolAddress(&p_q,   g_q);
    cudaGetSymbolAddress(&p_lat, g_lat);
    cudaGetSymbolAddress(&p_kvn, g_kvn);
    cudaGetSymbolAddress(&p_kv,  g_kv);
    cudaGetSymbolAddress(&p_kpe, g_kpe);
    cudaGetSymbolAddress(&p_att, g_att);
    float* qa  = (float*)p_qa;
    float* qb  = (float*)p_q;
    float* lat = (float*)p_lat;
    float* kvn = (float*)p_kvn;
    float* kv  = (float*)p_kv;
    float* kpe = (float*)p_kpe;
    float* att = (float*)p_att;

    const double mm = 0.1 * log(40.0) + 1.0;
    const float attn_scale = (float)(mm * mm / sqrt((double)QK));

    static int smem_set = 0;
    if (!smem_set) {
        cudaFuncSetAttribute(attn_kernel, cudaFuncAttributeMaxDynamicSharedMemorySize,
                             ATTN_SMEM_F4 * (int)sizeof(float4));
        smem_set = 1;
    }

    // q_a = hidden @ w_q_a   [2048x1536, K=5120]
    gemm_tc<128><<<dim3(QL / 128, T_TOK / 128), 256>>>(hidden, w_q_a, qa, T_TOK, QL, HID);
    // lat = hidden @ w_kv_a  [2048x576, K=5120]  (BN=64: 576 = 9*64)
    gemm_tc<64><<<dim3(LATW / 64, T_TOK / 128), 256>>>(hidden, w_kv_a, lat, T_TOK, LATW, HID);
    // rms(q_a) in place
    rmsnorm_kernel<<<T_TOK, 256>>>(qa, q_a_norm, qa, QL, QL, QL);
    // q = rms(q_a) @ w_q_b   [2048x3072, K=1536]
    gemm_tc<128><<<dim3(NHEAD * QK / 128, T_TOK / 128), 256>>>(qa, w_q_b, qb, T_TOK, NHEAD * QK, QL);
    // kvn = rms(lat[:, :KL])
    rmsnorm_kernel<<<T_TOK, 256>>>(lat, kv_a_norm, kvn, KL, LATW, KL);
    // kv = kvn @ w_kv_b      [2048x4096, K=512]
    gemm_tc<128><<<dim3(NHEAD * KVD / 128, T_TOK / 128), 256>>>(kvn, w_kv_b, kv, T_TOK, NHEAD * KVD, KL);
    // rope
    rope_kernel<<<T_TOK, 64>>>(positions, qb, lat, kpe);
    // attention
    attn_kernel<<<dim3(T_TOK / 16, NHEAD), 256,
                  ATTN_SMEM_F4 * sizeof(float4)>>>(qb, kv, kpe, att, attn_scale);
    // out = att @ w_o        [2048x5120, K=2048]
    gemm_tc<128><<<dim3(HID / 128, T_TOK / 128), 256>>>(att, w_o, out, T_TOK, HID, NHEAD * VD);
}

// round 6
// speedup vs baseline: 1.9061x; 1.4800x over previous
#include <cuda_runtime.h>
#include <cuda_bf16.h>
#include <math.h>
#include <stdint.h>

// ---------------------------------------------------------------------------
// Problem constants
// ---------------------------------------------------------------------------
#define T_TOK 2048
#define HID   5120
#define NHEAD 16
#define QL    1536
#define KL    512
#define NOPE  128
#define ROPE  64
#define VD    128
#define QK    192      // NOPE + ROPE
#define KVD   256      // NOPE + VD
#define LATW  576      // KL + ROPE

// ---------------------------------------------------------------------------
// Scratch (static device memory; no allocations allowed)
// ---------------------------------------------------------------------------
__device__ float g_qa  [T_TOK * QL];
__device__ float g_q   [T_TOK * NHEAD * QK];
__device__ float g_lat [T_TOK * LATW];
__device__ float g_kvn [T_TOK * KL];
__device__ float g_kv  [T_TOK * NHEAD * KVD];
__device__ float g_kpe [T_TOK * ROPE];
__device__ float g_att [T_TOK * NHEAD * VD];

// ---------------------------------------------------------------------------
// tf32 round-to-nearest (ties-to-even), pure integer ALU — no cvt instruction.
// ---------------------------------------------------------------------------
__device__ __forceinline__ uint32_t f2tf(float x) {
    uint32_t u = __float_as_uint(x);
    u += 0x1000u + ((u >> 13) & 1u);
    return u & 0xFFFFE000u;
}

// ---------------------------------------------------------------------------
// tf32 tensor-core GEMM: C[M,N] = A[M,K] @ B[K,N], row-major.
// BM=128, BK=16, BN template (128 or 64). 256 threads, 8 warps.
// Conservative design: no cp.async, no ldmatrix, static smem, register
// double-buffering of global loads; both operands tf32-rounded at staging.
// Requires M%128==0, N%BN==0, K%16==0 (holds for every GEMM here).
//
// smem layout: As[k][m] stride 136, Bs[k][n] stride 136/72.
// Fragment loads (m16n8k8): g=lane>>2, t4=lane&3.
//   a0=As[ks*8+t4][m0+mt*16+g]  a1=+8 rows(m)  a2=k+4  a3=both
//   b0=Bs[ks*8+t4][n0+nt*8+g]   b1=k+4
// Bank = (8*t4 + g + c) mod 32 -> conflict-free (stride % 32 == 8).
// ---------------------------------------------------------------------------
template<int BN>
__global__ __launch_bounds__(256, 2) void gemm_mma(
    const float* __restrict__ A, const float* __restrict__ B,
    float* __restrict__ C, int M, int N, int K)
{
    constexpr int BK = 16;
    constexpr int SA = 136;
    constexpr int SB = (BN == 128) ? 136 : 72;
    constexpr int WARPS_N = (BN == 128) ? 4 : 2;
    constexpr int WM = (BN == 128) ? 64 : 32;
    constexpr int MT = WM / 16;                 // 4 or 2
    constexpr int NT = 4;                       // WN = 32
    constexpr int BF4 = (BN == 128) ? 2 : 1;    // B float4 loads per thread

    __shared__ float As[BK][SA];
    __shared__ float Bs[BK][SB];

    const int tid  = threadIdx.x;
    const int warp = tid >> 5;
    const int lane = tid & 31;
    const int g    = lane >> 2;
    const int t4   = lane & 3;
    const int m0   = (warp / WARPS_N) * WM;
    const int n0   = (warp % WARPS_N) * 32;
    const int rowBase = blockIdx.y * 128;
    const int colBase = blockIdx.x * BN;

    // staging maps
    const int am    = tid >> 1;                 // 0..127
    const int akoff = (tid & 1) * 8;            // 0 or 8
    const int bk    = tid >> 4;                 // 0..15
    const int bn    = (tid & 15) * (4 * BF4);   // step 8 (BN=128) or 4 (BN=64)

    const float* Arow = A + (size_t)(rowBase + am) * K + akoff;
    const float* Bcol = B + (size_t)bk * N + colBase + bn;

    float acc[MT][NT][4];
    #pragma unroll
    for (int i = 0; i < MT; i++)
        #pragma unroll
        for (int j = 0; j < NT; j++)
            #pragma unroll
            for (int e = 0; e < 4; e++) acc[i][j][e] = 0.f;

    uint32_t aStg[8], bStg[4 * BF4];

    // ---- prologue: load tile 0 into regs, store to smem ----
    {
        float4 v0 = *reinterpret_cast<const float4*>(Arow);
        float4 v1 = *reinterpret_cast<const float4*>(Arow + 4);
        aStg[0] = f2tf(v0.x); aStg[1] = f2tf(v0.y); aStg[2] = f2tf(v0.z); aStg[3] = f2tf(v0.w);
        aStg[4] = f2tf(v1.x); aStg[5] = f2tf(v1.y); aStg[6] = f2tf(v1.z); aStg[7] = f2tf(v1.w);
        #pragma unroll
        for (int j = 0; j < BF4; j++) {
            float4 v = *reinterpret_cast<const float4*>(Bcol + 4 * j);
            bStg[4*j+0] = f2tf(v.x); bStg[4*j+1] = f2tf(v.y);
            bStg[4*j+2] = f2tf(v.z); bStg[4*j+3] = f2tf(v.w);
        }
        #pragma unroll
        for (int j = 0; j < 8; j++) As[akoff + j][am] = __uint_as_float(aStg[j]);
        #pragma unroll
        for (int j = 0; j < 4 * BF4; j++) Bs[bk][bn + j] = __uint_as_float(bStg[j]);
    }
    __syncthreads();

    const int nk = K / BK;
    for (int kt = 0; kt < nk; kt++) {
        const bool more = (kt + 1 < nk);
        if (more) {
            const float* ap = Arow + (kt + 1) * BK;
            float4 v0 = *reinterpret_cast<const float4*>(ap);
            float4 v1 = *reinterpret_cast<const float4*>(ap + 4);
            aStg[0] = f2tf(v0.x); aStg[1] = f2tf(v0.y); aStg[2] = f2tf(v0.z); aStg[3] = f2tf(v0.w);
            aStg[4] = f2tf(v1.x); aStg[5] = f2tf(v1.y); aStg[6] = f2tf(v1.z); aStg[7] = f2tf(v1.w);
            const float* bp = Bcol + (size_t)(kt + 1) * BK * N;
            #pragma unroll
            for (int j = 0; j < BF4; j++) {
                float4 v = *reinterpret_cast<const float4*>(bp + 4 * j);
                bStg[4*j+0] = f2tf(v.x); bStg[4*j+1] = f2tf(v.y);
                bStg[4*j+2] = f2tf(v.z); bStg[4*j+3] = f2tf(v.w);
            }
        }

        // ---- compute from smem ----
        #pragma unroll
        for (int ks = 0; ks < 2; ks++) {
            const int kA = ks * 8 + t4;
            uint32_t a[MT][4];
            uint32_t b[NT][2];
            #pragma unroll
            for (int mt = 0; mt < MT; mt++) {
                const int mm = m0 + mt * 16 + g;
                a[mt][0] = __float_as_uint(As[kA    ][mm    ]);
                a[mt][1] = __float_as_uint(As[kA    ][mm + 8]);
                a[mt][2] = __float_as_uint(As[kA + 4][mm    ]);
                a[mt][3] = __float_as_uint(As[kA + 4][mm + 8]);
            }
            #pragma unroll
            for (int nt = 0; nt < NT; nt++) {
                const int nn = n0 + nt * 8 + g;
                b[nt][0] = __float_as_uint(Bs[kA    ][nn]);
                b[nt][1] = __float_as_uint(Bs[kA + 4][nn]);
            }
            #pragma unroll
            for (int mt = 0; mt < MT; mt++)
                #pragma unroll
                for (int nt = 0; nt < NT; nt++)
                    asm volatile(
                        "mma.sync.aligned.m16n8k8.row.col.f32.tf32.tf32.f32 "
                        "{%0,%1,%2,%3}, {%4,%5,%6,%7}, {%8,%9}, {%0,%1,%2,%3};\n"
                        : "+f"(acc[mt][nt][0]), "+f"(acc[mt][nt][1]),
                          "+f"(acc[mt][nt][2]), "+f"(acc[mt][nt][3])
                        : "r"(a[mt][0]), "r"(a[mt][1]), "r"(a[mt][2]), "r"(a[mt][3]),
                          "r"(b[nt][0]), "r"(b[nt][1]));
        }

        __syncthreads();
        if (more) {
            #pragma unroll
            for (int j = 0; j < 8; j++) As[akoff + j][am] = __uint_as_float(aStg[j]);
            #pragma unroll
            for (int j = 0; j < 4 * BF4; j++) Bs[bk][bn + j] = __uint_as_float(bStg[j]);
            __syncthreads();
        }
    }

    // ---- epilogue ----
    #pragma unroll
    for (int mt = 0; mt < MT; mt++) {
        #pragma unroll
        for (int nt = 0; nt < NT; nt++) {
            const int row = rowBase + m0 + mt * 16 + g;
            const int col = colBase + n0 + nt * 8 + 2 * t4;
            *reinterpret_cast<float2*>(C + (size_t)row * N + col) =
                make_float2(acc[mt][nt][0], acc[mt][nt][1]);
            *reinterpret_cast<float2*>(C + (size_t)(row + 8) * N + col) =
                make_float2(acc[mt][nt][2], acc[mt][nt][3]);
        }
    }
}

// ---------------------------------------------------------------------------
// RMSNorm: one block per row.
// ---------------------------------------------------------------------------
__global__ __launch_bounds__(256) void rmsnorm_kernel(
    const float* __restrict__ x, const float* __restrict__ w,
    float* __restrict__ y, int width, int xstride, int ystride)
{
    const int row = blockIdx.x;
    const float* xr = x + (size_t)row * xstride;
    float* yr       = y + (size_t)row * ystride;

    float ss = 0.f;
    for (int i = threadIdx.x; i < width; i += blockDim.x) {
        float v = xr[i];
        ss += v * v;
    }
    __shared__ float red[8];
    for (int o = 16; o; o >>= 1) ss += __shfl_xor_sync(0xffffffffu, ss, o);
    if ((threadIdx.x & 31) == 0) red[threadIdx.x >> 5] = ss;
    __syncthreads();
    __shared__ float s_r;
    if (threadIdx.x == 0) {
        float tot = 0.f;
        for (int i = 0; i < (int)(blockDim.x >> 5); i++) tot += red[i];
        s_r = rsqrtf(tot / (float)width + 1e-6f);
    }
    __syncthreads();
    float r = s_r;
    for (int i = threadIdx.x; i < width; i += blockDim.x)
        yr[i] = xr[i] * r * w[i];
}

// ---------------------------------------------------------------------------
// RoPE (YaRN), double-precision inv_freq to match numpy path.
// ---------------------------------------------------------------------------
__global__ __launch_bounds__(64) void rope_kernel(
    const int* __restrict__ positions,
    float* __restrict__ q,
    const float* __restrict__ lat,
    float* __restrict__ kpe)
{
    const int t = blockIdx.x;
    __shared__ float cs[32], sn[32];

    if (threadIdx.x < 32) {
        int i = threadIdx.x;
        double pf    = pow(10000.0, (double)(2 * i) / (double)ROPE);
        double extra = 1.0 / pf;
        double inter = 1.0 / (40.0 * pf);
        double lowd  = floor((double)ROPE * log(4096.0 / (32.0 * 2.0 * M_PI)) / (2.0 * log(10000.0)));
        double highd = ceil ((double)ROPE * log(4096.0 / ( 1.0 * 2.0 * M_PI)) / (2.0 * log(10000.0)));
        if (lowd < 0.0) lowd = 0.0;
        if (highd > (double)(ROPE - 1)) highd = (double)(ROPE - 1);
        double denom = highd - lowd; if (denom < 0.001) denom = 0.001;
        double ramp  = ((double)i - lowd) / denom;
        if (ramp < 0.0) ramp = 0.0;
        if (ramp > 1.0) ramp = 1.0;
        double mask = 1.0 - ramp;
        float invf = (float)(inter * (1.0 - mask) + extra * mask);

        float freq = (float)positions[t] * invf;
        cs[i] = (float)cos((double)freq);
        sn[i] = (float)sin((double)freq);
    }
    __syncthreads();

    for (int p = threadIdx.x; p < (NHEAD + 1) * 32; p += 64) {
        int i = p & 31;
        int h = p >> 5;
        float c = cs[i], s = sn[i];
        if (h < NHEAD) {
            float* base = q + ((size_t)t * NHEAD + h) * QK + NOPE + 2 * i;
            float x1 = base[0], x2 = base[1];
            base[0] = x1 * c - x2 * s;
            base[1] = x2 * c + x1 * s;
        } else {
            const float* kb = lat + (size_t)t * LATW + KL + 2 * i;
            float x1 = kb[0], x2 = kb[1];
            kpe[(size_t)t * ROPE + 2 * i]     = x1 * c - x2 * s;
            kpe[(size_t)t * ROPE + 2 * i + 1] = x2 * c + x1 * s;
        }
    }
}

// ---------------------------------------------------------------------------
// Causal flash attention, fp32, fully float4 (round-2 passing version).
// ---------------------------------------------------------------------------
#define ATTN_SMEM_F4 (16 * 49 + 32 * 49 + 32 * 33)

__global__ __launch_bounds__(256) void attn_kernel(
    const float* __restrict__ q,
    const float* __restrict__ kv,
    const float* __restrict__ kpe,
    float* __restrict__ out,
    float scale)
{
    extern __shared__ float4 sm4[];
    float4* Qs = sm4;
    float4* Ks = sm4 + 16 * 49;
    float4* Vs = sm4 + 16 * 49 + 32 * 49;

    const int h    = blockIdx.y;
    const int q0   = blockIdx.x * 16;
    const int tid  = threadIdx.x;
    const int w    = tid >> 5;
    const int lane = tid & 31;
    const int qiA  = q0 + 2 * w;
    const int qiB  = qiA + 1;

    for (int idx = tid; idx < 16 * 48; idx += 256) {
        int r = idx / 48, d = idx - r * 48;
        Qs[r * 49 + d] =
            reinterpret_cast<const float4*>(q + ((size_t)(q0 + r) * NHEAD + h) * QK)[d];
    }

    float4 accA = make_float4(0.f, 0.f, 0.f, 0.f);
    float4 accB = make_float4(0.f, 0.f, 0.f, 0.f);
    float mA = -1e30f, lA = 0.f, mB = -1e30f, lB = 0.f;

    const int nkb = (q0 + 15) / 32 + 1;
    for (int kb = 0; kb < nkb; kb++) {
        const int k0 = kb * 32;
        __syncthreads();
        for (int idx = tid; idx < 32 * 48; idx += 256) {
            int r = idx / 48, d = idx - r * 48;
            float4 v;
            if (d < 32)
                v = reinterpret_cast<const float4*>(kv + ((size_t)(k0 + r) * NHEAD + h) * KVD)[d];
            else
                v = reinterpret_cast<const float4*>(kpe + (size_t)(k0 + r) * ROPE)[d - 32];
            Ks[r * 49 + d] = v;
        }
        for (int idx = tid; idx < 32 * 32; idx += 256) {
            int r = idx >> 5, d = idx & 31;
            Vs[r * 33 + d] =
                reinterpret_cast<const float4*>(kv + ((size_t)(k0 + r) * NHEAD + h) * KVD + NOPE)[d];
        }
        __syncthreads();

        float sA = 0.f, sB = 0.f;
        const float4* kr  = &Ks[lane * 49];
        const float4* qr0 = &Qs[(2 * w) * 49];
        const float4* qr1 = &Qs[(2 * w + 1) * 49];
        #pragma unroll
        for (int d = 0; d < 48; d++) {
            float4 kvv = kr[d];
            float4 q1 = qr0[d];
            float4 q2 = qr1[d];
            sA += q1.x * kvv.x + q1.y * kvv.y + q1.z * kvv.z + q1.w * kvv.w;
            sB += q2.x * kvv.x + q2.y * kvv.y + q2.z * kvv.z + q2.w * kvv.w;
        }
        sA *= scale; sB *= scale;
        const int kidx = k0 + lane;
        if (kidx > qiA) sA = -1e30f;
        if (kidx > qiB) sB = -1e30f;

        float mbA = sA, mbB = sB;
        #pragma unroll
        for (int o = 16; o; o >>= 1) {
            mbA = fmaxf(mbA, __shfl_xor_sync(0xffffffffu, mbA, o));
            mbB = fmaxf(mbB, __shfl_xor_sync(0xffffffffu, mbB, o));
        }
        float mnA = fmaxf(mA, mbA), mnB = fmaxf(mB, mbB);
        float pA = __expf(sA - mnA), pB = __expf(sB - mnB);
        float psA = pA, psB = pB;
        #pragma unroll
        for (int o = 16; o; o >>= 1) {
            psA += __shfl_xor_sync(0xffffffffu, psA, o);
            psB += __shfl_xor_sync(0xffffffffu, psB, o);
        }
        float aA = __expf(mA - mnA), aB = __expf(mB - mnB);
        lA = lA * aA + psA;  lB = lB * aB + psB;
        accA.x *= aA; accA.y *= aA; accA.z *= aA; accA.w *= aA;
        accB.x *= aB; accB.y *= aB; accB.z *= aB; accB.w *= aB;
        mA = mnA; mB = mnB;

        #pragma unroll
        for (int j = 0; j < 32; j++) {
            float pjA = __shfl_sync(0xffffffffu, pA, j);
            float pjB = __shfl_sync(0xffffffffu, pB, j);
            float4 vv = Vs[j * 33 + lane];
            accA.x += pjA * vv.x; accA.y += pjA * vv.y;
            accA.z += pjA * vv.z; accA.w += pjA * vv.w;
            accB.x += pjB * vv.x; accB.y += pjB * vv.y;
            accB.z += pjB * vv.z; accB.w += pjB * vv.w;
        }
    }

    const float ivA = 1.f / lA, ivB = 1.f / lB;
    float4 oA = make_float4(accA.x * ivA, accA.y * ivA, accA.z * ivA, accA.w * ivA);
    float4 oB = make_float4(accB.x * ivB, accB.y * ivB, accB.z * ivB, accB.w * ivB);
    *reinterpret_cast<float4*>(out + (size_t)qiA * (NHEAD * VD) + (size_t)h * VD + lane * 4) = oA;
    *reinterpret_cast<float4*>(out + (size_t)qiB * (NHEAD * VD) + (size_t)h * VD + lane * 4) = oB;
}

// ---------------------------------------------------------------------------
// Launch
// ---------------------------------------------------------------------------
extern "C" void kernel_launch(void* const* d_in, const int* in_sizes, int n_in,
                              void* d_out, int out_size)
{
    const int*   positions = (const int*)  d_in[0];
    const float* hidden    = (const float*)d_in[1];
    const float* w_q_a     = (const float*)d_in[2];
    const float* q_a_norm  = (const float*)d_in[3];
    const float* w_q_b     = (const float*)d_in[4];
    const float* w_kv_a    = (const float*)d_in[5];
    const float* kv_a_norm = (const float*)d_in[6];
    const float* w_kv_b    = (const float*)d_in[7];
    const float* w_o       = (const float*)d_in[8];
    float* out = (float*)d_out;

    void *p_qa, *p_q, *p_lat, *p_kvn, *p_kv, *p_kpe, *p_att;
    cudaGetSymbolAddress(&p_qa,  g_qa);
    cudaGetSymbolAddress(&p_q,   g_q);
    cudaGetSymbolAddress(&p_lat, g_lat);
    cudaGetSymbolAddress(&p_kvn, g_kvn);
    cudaGetSymbolAddress(&p_kv,  g_kv);
    cudaGetSymbolAddress(&p_kpe, g_kpe);
    cudaGetSymbolAddress(&p_att, g_att);
    float* qa  = (float*)p_qa;
    float* qb  = (float*)p_q;
    float* lat = (float*)p_lat;
    float* kvn = (float*)p_kvn;
    float* kv  = (float*)p_kv;
    float* kpe = (float*)p_kpe;
    float* att = (float*)p_att;

    const double mm = 0.1 * log(40.0) + 1.0;
    const float attn_scale = (float)(mm * mm / sqrt((double)QK));

    static int smem_set = 0;
    if (!smem_set) {
        cudaFuncSetAttribute(attn_kernel, cudaFuncAttributeMaxDynamicSharedMemorySize,
                             ATTN_SMEM_F4 * (int)sizeof(float4));
        smem_set = 1;
    }

    // q_a = hidden @ w_q_a   [2048x1536, K=5120]
    gemm_mma<128><<<dim3(QL / 128, T_TOK / 128), 256>>>(hidden, w_q_a, qa, T_TOK, QL, HID);
    // lat = hidden @ w_kv_a  [2048x576, K=5120]
    gemm_mma<64><<<dim3(LATW / 64, T_TOK / 128), 256>>>(hidden, w_kv_a, lat, T_TOK, LATW, HID);
    // rms(q_a) in place
    rmsnorm_kernel<<<T_TOK, 256>>>(qa, q_a_norm, qa, QL, QL, QL);
    // q = rms(q_a) @ w_q_b   [2048x3072, K=1536]
    gemm_mma<128><<<dim3(NHEAD * QK / 128, T_TOK / 128), 256>>>(qa, w_q_b, qb, T_TOK, NHEAD * QK, QL);
    // kvn = rms(lat[:, :KL])
    rmsnorm_kernel<<<T_TOK, 256>>>(lat, kv_a_norm, kvn, KL, LATW, KL);
    // kv = kvn @ w_kv_b      [2048x4096, K=512]
    gemm_mma<128><<<dim3(NHEAD * KVD / 128, T_TOK / 128), 256>>>(kvn, w_kv_b, kv, T_TOK, NHEAD * KVD, KL);
    // rope
    rope_kernel<<<T_TOK, 64>>>(positions, qb, lat, kpe);
    // attention
    attn_kernel<<<dim3(T_TOK / 16, NHEAD), 256,
                  ATTN_SMEM_F4 * sizeof(float4)>>>(qb, kv, kpe, att, attn_scale);
    // out = att @ w_o        [2048x5120, K=2048]
    gemm_mma<128><<<dim3(HID / 128, T_TOK / 128), 256>>>(att, w_o, out, T_TOK, HID, NHEAD * VD);
}